// round 2
// baseline (speedup 1.0000x reference)
#include <cuda_runtime.h>
#include <cuda_bf16.h>
#include <cstdint>

// Problem constants
#define BB   256   // batch
#define TT   512   // time
#define II   300   // input size
#define HH   64    // hidden
#define G3   192   // 3*H

// Scratch: xp[dir][s][b][g]  (dir0 = forward scan order, dir1 = backward scan order)
__device__ float g_xp[2ull * TT * BB * G3];        // 201 MB
__device__ float g_feat[BB * 256];                 // [B, 4H]

// ---------------------------------------------------------------------------
// Kernel 1: input projection GEMM.
// M = B*T = 131072 rows of x, N = 384 (192 fwd gates | 192 bwd gates), K = 300.
// Block tile 128x128, thread tile 8x8, K chunk 20 (300 = 15*20).
// ---------------------------------------------------------------------------
__global__ void __launch_bounds__(256)
proj_kernel(const float* __restrict__ x,
            const float* __restrict__ Wf, const float* __restrict__ bf,
            const float* __restrict__ Wb, const float* __restrict__ bb)
{
    __shared__ float As[20][132];   // [k][m]
    __shared__ float Bs[20][132];   // [k][n]

    const int tid = threadIdx.x;
    const int tx  = tid & 15;       // n: 8 cols each
    const int ty  = tid >> 4;       // m: 8 rows each
    const int mt  = blockIdx.x;     // 0..1023
    const int nt  = blockIdx.y;     // 0..2

    const int r0 = mt * 128;
    const int n0 = nt * 128;

    float acc[8][8];
    #pragma unroll
    for (int i = 0; i < 8; i++)
        #pragma unroll
        for (int j = 0; j < 8; j++) acc[i][j] = 0.f;

    for (int k0 = 0; k0 < II; k0 += 20) {
        // A tile: 128 rows x 20 k = 640 float4.  B tile: same. 1280 total.
        for (int i = tid; i < 1280; i += 256) {
            if (i < 640) {
                const int row = i / 5, q = i % 5;
                float4 v = *(const float4*)(x + (size_t)(r0 + row) * II + k0 + q * 4);
                As[q*4+0][row] = v.x; As[q*4+1][row] = v.y;
                As[q*4+2][row] = v.z; As[q*4+3][row] = v.w;
            } else {
                const int ii = i - 640;
                const int row = ii / 5, q = ii % 5;     // row = local col index
                const int col = n0 + row;
                const float* W = (col < G3) ? Wf : Wb;
                const int g = (col < G3) ? col : col - G3;
                float4 v = *(const float4*)(W + (size_t)g * II + k0 + q * 4);
                Bs[q*4+0][row] = v.x; Bs[q*4+1][row] = v.y;
                Bs[q*4+2][row] = v.z; Bs[q*4+3][row] = v.w;
            }
        }
        __syncthreads();

        #pragma unroll
        for (int k = 0; k < 20; k++) {
            float4 a0 = *(const float4*)&As[k][ty * 8];
            float4 a1 = *(const float4*)&As[k][ty * 8 + 4];
            float4 b0 = *(const float4*)&Bs[k][tx * 8];
            float4 b1 = *(const float4*)&Bs[k][tx * 8 + 4];
            float am[8] = {a0.x, a0.y, a0.z, a0.w, a1.x, a1.y, a1.z, a1.w};
            float bn[8] = {b0.x, b0.y, b0.z, b0.w, b1.x, b1.y, b1.z, b1.w};
            #pragma unroll
            for (int i = 0; i < 8; i++)
                #pragma unroll
                for (int j = 0; j < 8; j++)
                    acc[i][j] += am[i] * bn[j];
        }
        __syncthreads();
    }

    // bias + store in scan order. Thread's 8 cols never straddle the 192 split
    // (cols = n0 + tx*8 .. +7; 192 is a multiple of 8).
    const int c0  = n0 + tx * 8;
    const int dir = (c0 >= G3) ? 1 : 0;
    const int g0  = c0 - dir * G3;
    const float* bias = dir ? bb : bf;
    float bs[8];
    #pragma unroll
    for (int j = 0; j < 8; j++) bs[j] = bias[g0 + j];

    #pragma unroll
    for (int i = 0; i < 8; i++) {
        const int r = r0 + ty * 8 + i;
        const int b = r >> 9;          // / 512
        const int t = r & 511;
        const int s = dir ? (TT - 1 - t) : t;
        size_t idx = (((size_t)dir * TT + s) * BB + b) * G3 + g0;
        float4 o0, o1;
        o0.x = acc[i][0] + bs[0]; o0.y = acc[i][1] + bs[1];
        o0.z = acc[i][2] + bs[2]; o0.w = acc[i][3] + bs[3];
        o1.x = acc[i][4] + bs[4]; o1.y = acc[i][5] + bs[5];
        o1.z = acc[i][6] + bs[6]; o1.w = acc[i][7] + bs[7];
        *(float4*)&g_xp[idx]     = o0;
        *(float4*)&g_xp[idx + 4] = o1;
    }
}

// ---------------------------------------------------------------------------
// Kernel 2: GRU recurrence.
// Block = 384 threads = 2 groups x 192; each group runs one (dir,batch) chain.
// 12 warps -> exactly 3 per SMSP (balanced). Thread j owns W_hh row j in
// 64 registers; h[64] broadcast from smem; next-step xp prefetched.
// ---------------------------------------------------------------------------
__device__ __forceinline__ float sigmoid_fast(float a) {
    return 1.f / (1.f + __expf(-a));
}
__device__ __forceinline__ float tanh_fast(float a) {
    float c = fminf(fmaxf(a, -20.f), 20.f);
    float e = __expf(2.f * c);
    return (e - 1.f) / (e + 1.f);
}

__global__ void __launch_bounds__(384, 2)
gru_kernel(const float* __restrict__ Whh_f, const float* __restrict__ bhh_f,
           const float* __restrict__ Whh_b, const float* __restrict__ bhh_b)
{
    __shared__ __align__(16) float sh_h[2][64];
    __shared__ float s_r[2][64], s_z[2][64], s_gn[2][64], s_xn[2][64];

    const int grp   = threadIdx.x / 192;        // 0 or 1
    const int j     = threadIdx.x % 192;
    const int chain = blockIdx.x * 2 + grp;     // 0..511
    const int dir   = chain >> 8;
    const int b     = chain & 255;

    const float* W  = dir ? Whh_b : Whh_f;
    const float* bh = dir ? bhh_b : bhh_f;

    float w[64];
    #pragma unroll
    for (int k = 0; k < 64; k += 4) {
        float4 v = *(const float4*)(W + (size_t)j * 64 + k);
        w[k] = v.x; w[k+1] = v.y; w[k+2] = v.z; w[k+3] = v.w;
    }
    const float bias = bh[j];

    if (j < 64) sh_h[grp][j] = 0.f;
    __syncthreads();

    const float* xp_p = g_xp + ((size_t)dir * TT) * BB * G3 + (size_t)b * G3 + j;
    const size_t stride = (size_t)BB * G3;

    float xp = __ldg(xp_p);

    for (int s = 0; s < TT; s++) {
        // Prefetch next step's input projection (hides DRAM latency behind dot)
        float xp_next = 0.f;
        if (s + 1 < TT) xp_next = __ldg(xp_p + (size_t)(s + 1) * stride);

        float a0 = 0.f, a1 = 0.f, a2 = 0.f, a3 = 0.f;
        #pragma unroll
        for (int k = 0; k < 64; k += 4) {
            float4 h4 = *(const float4*)&sh_h[grp][k];
            a0 += w[k]     * h4.x;
            a1 += w[k + 1] * h4.y;
            a2 += w[k + 2] * h4.z;
            a3 += w[k + 3] * h4.w;
        }
        const float gh = bias + ((a0 + a1) + (a2 + a3));
        const float a  = xp + gh;

        if (j < 64)        s_r[grp][j]        = sigmoid_fast(a);
        else if (j < 128)  s_z[grp][j - 64]   = sigmoid_fast(a);
        else             { s_gn[grp][j - 128] = gh; s_xn[grp][j - 128] = xp; }
        __syncthreads();

        if (j < 64) {
            const float r    = s_r[grp][j];
            const float z    = s_z[grp][j];
            const float n    = tanh_fast(s_xn[grp][j] + r * s_gn[grp][j]);
            const float hold = sh_h[grp][j];
            const float hnew = (1.f - z) * n + z * hold;
            sh_h[grp][j] = hnew;
            if (s == 0)
                g_feat[b * 256 + (dir ? 192 : 0) + j] = hnew;  // hs_f[0] / hs_b[0]
        }
        __syncthreads();

        xp = xp_next;
    }

    if (j < 64)
        g_feat[b * 256 + (dir ? 64 : 128) + j] = sh_h[grp][j];  // final h
}

// ---------------------------------------------------------------------------
// Kernel 3: head. One warp per batch row.
// ---------------------------------------------------------------------------
__global__ void __launch_bounds__(32)
head_kernel(const float* __restrict__ W1, const float* __restrict__ b1,
            const float* __restrict__ W2, const float* __restrict__ b2,
            float* __restrict__ out)
{
    const int b = blockIdx.x;
    const int j = threadIdx.x;   // 0..31
    const float* f = g_feat + b * 256;
    const float* w = W1 + (size_t)j * 256;

    float acc = b1[j];
    #pragma unroll 8
    for (int k = 0; k < 256; k += 4) {
        float4 fv = *(const float4*)(f + k);
        float4 wv = *(const float4*)(w + k);
        acc += fv.x * wv.x + fv.y * wv.y + fv.z * wv.z + fv.w * wv.w;
    }
    acc = (acc >= 0.f) ? acc : 0.01f * acc;   // LeakyReLU
    float v = acc * W2[j];
    #pragma unroll
    for (int off = 16; off; off >>= 1)
        v += __shfl_down_sync(0xffffffffu, v, off);
    if (j == 0) out[b] = v + b2[0];
}

// ---------------------------------------------------------------------------
extern "C" void kernel_launch(void* const* d_in, const int* in_sizes, int n_in,
                              void* d_out, int out_size)
{
    const float* x      = (const float*)d_in[0];
    const float* W_ih_f = (const float*)d_in[1];
    const float* W_hh_f = (const float*)d_in[2];
    const float* b_ih_f = (const float*)d_in[3];
    const float* b_hh_f = (const float*)d_in[4];
    const float* W_ih_b = (const float*)d_in[5];
    const float* W_hh_b = (const float*)d_in[6];
    const float* b_ih_b = (const float*)d_in[7];
    const float* b_hh_b = (const float*)d_in[8];
    const float* W1     = (const float*)d_in[9];
    const float* b1     = (const float*)d_in[10];
    const float* W2     = (const float*)d_in[11];
    const float* b2     = (const float*)d_in[12];
    float* out = (float*)d_out;

    proj_kernel<<<dim3(1024, 3), 256>>>(x, W_ih_f, b_ih_f, W_ih_b, b_ih_b);
    gru_kernel<<<256, 384>>>(W_hh_f, b_hh_f, W_hh_b, b_hh_b);
    head_kernel<<<256, 32>>>(W1, b1, W2, b2, out);
}

// round 3
// speedup vs baseline: 1.1261x; 1.1261x over previous
#include <cuda_runtime.h>
#include <cuda_bf16.h>
#include <cstdint>

// Problem constants
#define BB   256   // batch
#define TT   512   // time
#define II   300   // input size
#define HH   64    // hidden
#define G3   192   // 3*H

typedef unsigned long long ull;

// Scratch: xp[dir][s][b][g]  (dir0 = forward scan order, dir1 = backward scan order)
__device__ float g_xp[2ull * TT * BB * G3];        // 201 MB
__device__ float g_feat[BB * 256];                 // [B, 4H]

// ---------------------------------------------------------------------------
// f32x2 helpers (Blackwell packed fp32 — FFMA2, only reachable via PTX)
// ---------------------------------------------------------------------------
__device__ __forceinline__ ull ffma2(ull a, ull b, ull c) {
    ull d;
    asm("fma.rn.f32x2 %0, %1, %2, %3;" : "=l"(d) : "l"(a), "l"(b), "l"(c));
    return d;
}
__device__ __forceinline__ ull dup2(float a) {
    ull d; unsigned au = __float_as_uint(a);
    asm("mov.b64 %0, {%1, %1};" : "=l"(d) : "r"(au));
    return d;
}
union F2U { ull u; float2 f; };
__device__ __forceinline__ float hsum2(ull a) { F2U t; t.u = a; return t.f.x + t.f.y; }

// ---------------------------------------------------------------------------
// Kernel 1: input projection GEMM with FFMA2.
// M = B*T = 131072 rows of x, N = 384 (192 fwd | 192 bwd), K = 300.
// Block tile 128x128, thread tile 8x8 (stored as 8x4 f32x2 pairs), K chunk 20.
// ---------------------------------------------------------------------------
__global__ void __launch_bounds__(256)
proj_kernel(const float* __restrict__ x,
            const float* __restrict__ Wf, const float* __restrict__ bf,
            const float* __restrict__ Wb, const float* __restrict__ bb)
{
    __shared__ __align__(16) float As[20][136];   // [k][m], row = 544B (16B mult)
    __shared__ __align__(16) float Bs[20][136];   // [k][n]

    const int tid = threadIdx.x;
    const int tx  = tid & 15;       // n: 8 cols each
    const int ty  = tid >> 4;       // m: 8 rows each
    const int mt  = blockIdx.x;     // 0..1023
    const int nt  = blockIdx.y;     // 0..2

    const int r0 = mt * 128;
    const int n0 = nt * 128;

    ull acc2[8][4];
    #pragma unroll
    for (int i = 0; i < 8; i++)
        #pragma unroll
        for (int j = 0; j < 4; j++) acc2[i][j] = 0ull;

    for (int k0 = 0; k0 < II; k0 += 20) {
        // A tile: 128 rows x 20 k = 640 float4.  B tile: same. 1280 total.
        for (int i = tid; i < 1280; i += 256) {
            if (i < 640) {
                const int row = i / 5, q = i % 5;
                float4 v = *(const float4*)(x + (size_t)(r0 + row) * II + k0 + q * 4);
                As[q*4+0][row] = v.x; As[q*4+1][row] = v.y;
                As[q*4+2][row] = v.z; As[q*4+3][row] = v.w;
            } else {
                const int ii = i - 640;
                const int row = ii / 5, q = ii % 5;     // row = local col index
                const int col = n0 + row;
                const float* W = (col < G3) ? Wf : Wb;
                const int g = (col < G3) ? col : col - G3;
                float4 v = *(const float4*)(W + (size_t)g * II + k0 + q * 4);
                Bs[q*4+0][row] = v.x; Bs[q*4+1][row] = v.y;
                Bs[q*4+2][row] = v.z; Bs[q*4+3][row] = v.w;
            }
        }
        __syncthreads();

        #pragma unroll
        for (int k = 0; k < 20; k++) {
            float4 a0 = *(const float4*)&As[k][ty * 8];
            float4 a1 = *(const float4*)&As[k][ty * 8 + 4];
            ulonglong2 bA = *(const ulonglong2*)&Bs[k][tx * 8];      // pairs (b0,b1),(b2,b3)
            ulonglong2 bB = *(const ulonglong2*)&Bs[k][tx * 8 + 4];  // pairs (b4,b5),(b6,b7)
            float am[8] = {a0.x, a0.y, a0.z, a0.w, a1.x, a1.y, a1.z, a1.w};
            #pragma unroll
            for (int i = 0; i < 8; i++) {
                const ull ap = dup2(am[i]);
                acc2[i][0] = ffma2(ap, bA.x, acc2[i][0]);
                acc2[i][1] = ffma2(ap, bA.y, acc2[i][1]);
                acc2[i][2] = ffma2(ap, bB.x, acc2[i][2]);
                acc2[i][3] = ffma2(ap, bB.y, acc2[i][3]);
            }
        }
        __syncthreads();
    }

    // bias + store in scan order. Thread's 8 cols never straddle the 192 split.
    const int c0  = n0 + tx * 8;
    const int dir = (c0 >= G3) ? 1 : 0;
    const int g0  = c0 - dir * G3;
    const float* bias = dir ? bb : bf;
    float bs[8];
    #pragma unroll
    for (int j = 0; j < 8; j++) bs[j] = bias[g0 + j];

    #pragma unroll
    for (int i = 0; i < 8; i++) {
        const int r = r0 + ty * 8 + i;
        const int b = r >> 9;          // / 512
        const int t = r & 511;
        const int s = dir ? (TT - 1 - t) : t;
        size_t idx = (((size_t)dir * TT + s) * BB + b) * G3 + g0;
        F2U p0, p1, p2, p3;
        p0.u = acc2[i][0]; p1.u = acc2[i][1]; p2.u = acc2[i][2]; p3.u = acc2[i][3];
        float4 o0, o1;
        o0.x = p0.f.x + bs[0]; o0.y = p0.f.y + bs[1];
        o0.z = p1.f.x + bs[2]; o0.w = p1.f.y + bs[3];
        o1.x = p2.f.x + bs[4]; o1.y = p2.f.y + bs[5];
        o1.z = p3.f.x + bs[6]; o1.w = p3.f.y + bs[7];
        *(float4*)&g_xp[idx]     = o0;
        *(float4*)&g_xp[idx + 4] = o1;
    }
}

// ---------------------------------------------------------------------------
// Kernel 2: GRU recurrence.
// Block = 256 threads = 4 independent 64-thread chain groups (named barriers).
// Thread j of a group owns h_j: keeps W_hh rows j, j+64, j+128 in registers
// as f32x2 pairs (96 FFMA2/step), computes all 3 gates itself, h double-
// buffered in smem -> ONE bar.sync per step. h loads are pure broadcast.
// ---------------------------------------------------------------------------
__device__ __forceinline__ float sigmoid_fast(float a) {
    return 1.f / (1.f + __expf(-a));
}
__device__ __forceinline__ float tanh_fast(float a) {
    float c = fminf(fmaxf(a, -20.f), 20.f);
    float e = __expf(2.f * c);
    return (e - 1.f) / (e + 1.f);
}

__global__ void __launch_bounds__(256)
gru_kernel(const float* __restrict__ Whh_f, const float* __restrict__ bhh_f,
           const float* __restrict__ Whh_b, const float* __restrict__ bhh_b)
{
    __shared__ __align__(16) float sh_h[4][2][64];   // [group][pingpong][unit]

    const int grp   = threadIdx.x >> 6;          // 0..3
    const int j     = threadIdx.x & 63;          // h unit
    const int chain = blockIdx.x * 4 + grp;      // 0..511
    const int dir   = chain >> 8;
    const int b     = chain & 255;
    const int bar   = grp + 1;                   // named barrier id 1..4

    const float* W  = dir ? Whh_b : Whh_f;
    const float* bh = dir ? bhh_b : bhh_f;

    // Weights: 3 rows x 64 = 96 f32x2 pairs in registers
    ull wr[32], wz[32], wn[32];
    {
        const ull* Rr = (const ull*)(W + (size_t)j * 64);
        const ull* Rz = (const ull*)(W + (size_t)(j + 64) * 64);
        const ull* Rn = (const ull*)(W + (size_t)(j + 128) * 64);
        #pragma unroll
        for (int k = 0; k < 32; k++) { wr[k] = Rr[k]; wz[k] = Rz[k]; wn[k] = Rn[k]; }
    }
    const float br = bh[j], bz = bh[j + 64], bn = bh[j + 128];

    sh_h[grp][0][j] = 0.f;
    float h_old = 0.f;

    const float* xp_b = g_xp + ((size_t)dir * TT * BB + b) * G3;
    const size_t stride = (size_t)BB * G3;

    float xr = __ldg(xp_b + j);
    float xz = __ldg(xp_b + j + 64);
    float xn = __ldg(xp_b + j + 128);

    asm volatile("bar.sync %0, 64;" :: "r"(bar) : "memory");

    #pragma unroll 1
    for (int s = 0; s < TT; s++) {
        // prefetch next step's projections
        float nxr = 0.f, nxz = 0.f, nxn = 0.f;
        if (s + 1 < TT) {
            const float* p = xp_b + (size_t)(s + 1) * stride;
            nxr = __ldg(p + j); nxz = __ldg(p + j + 64); nxn = __ldg(p + j + 128);
        }

        const int p = s & 1;
        const ulonglong2* hp = (const ulonglong2*)sh_h[grp][p];
        ull ar = 0ull, az = 0ull, an = 0ull;
        #pragma unroll
        for (int k = 0; k < 16; k++) {
            ulonglong2 h2 = hp[k];
            ar = ffma2(wr[2*k],   h2.x, ar);
            az = ffma2(wz[2*k],   h2.x, az);
            an = ffma2(wn[2*k],   h2.x, an);
            ar = ffma2(wr[2*k+1], h2.y, ar);
            az = ffma2(wz[2*k+1], h2.y, az);
            an = ffma2(wn[2*k+1], h2.y, an);
        }
        const float gr = hsum2(ar) + br;
        const float gz = hsum2(az) + bz;
        const float gn = hsum2(an) + bn;

        const float r = sigmoid_fast(xr + gr);
        const float z = sigmoid_fast(xz + gz);
        const float n = tanh_fast(xn + r * gn);
        const float hnew = (1.f - z) * n + z * h_old;

        sh_h[grp][1 - p][j] = hnew;
        h_old = hnew;
        if (s == 0)
            g_feat[b * 256 + (dir ? 192 : 0) + j] = hnew;   // hs_f[0] / hs_b[0]

        asm volatile("bar.sync %0, 64;" :: "r"(bar) : "memory");

        xr = nxr; xz = nxz; xn = nxn;
    }

    g_feat[b * 256 + (dir ? 64 : 128) + j] = h_old;          // final h
}

// ---------------------------------------------------------------------------
// Kernel 3: head. One warp per batch row.
// ---------------------------------------------------------------------------
__global__ void __launch_bounds__(32)
head_kernel(const float* __restrict__ W1, const float* __restrict__ b1,
            const float* __restrict__ W2, const float* __restrict__ b2,
            float* __restrict__ out)
{
    const int b = blockIdx.x;
    const int j = threadIdx.x;   // 0..31
    const float* f = g_feat + b * 256;
    const float* w = W1 + (size_t)j * 256;

    float acc = b1[j];
    #pragma unroll 8
    for (int k = 0; k < 256; k += 4) {
        float4 fv = *(const float4*)(f + k);
        float4 wv = *(const float4*)(w + k);
        acc += fv.x * wv.x + fv.y * wv.y + fv.z * wv.z + fv.w * wv.w;
    }
    acc = (acc >= 0.f) ? acc : 0.01f * acc;   // LeakyReLU
    float v = acc * W2[j];
    #pragma unroll
    for (int off = 16; off; off >>= 1)
        v += __shfl_down_sync(0xffffffffu, v, off);
    if (j == 0) out[b] = v + b2[0];
}

// ---------------------------------------------------------------------------
extern "C" void kernel_launch(void* const* d_in, const int* in_sizes, int n_in,
                              void* d_out, int out_size)
{
    const float* x      = (const float*)d_in[0];
    const float* W_ih_f = (const float*)d_in[1];
    const float* W_hh_f = (const float*)d_in[2];
    const float* b_ih_f = (const float*)d_in[3];
    const float* b_hh_f = (const float*)d_in[4];
    const float* W_ih_b = (const float*)d_in[5];
    const float* W_hh_b = (const float*)d_in[6];
    const float* b_ih_b = (const float*)d_in[7];
    const float* b_hh_b = (const float*)d_in[8];
    const float* W1     = (const float*)d_in[9];
    const float* b1     = (const float*)d_in[10];
    const float* W2     = (const float*)d_in[11];
    const float* b2     = (const float*)d_in[12];
    float* out = (float*)d_out;

    proj_kernel<<<dim3(1024, 3), 256>>>(x, W_ih_f, b_ih_f, W_ih_b, b_ih_b);
    gru_kernel<<<128, 256>>>(W_hh_f, b_hh_f, W_hh_b, b_hh_b);
    head_kernel<<<256, 32>>>(W1, b1, W2, b2, out);
}

// round 6
// speedup vs baseline: 1.6931x; 1.5035x over previous
#include <cuda_runtime.h>
#include <cuda_bf16.h>
#include <cstdint>

#define BB   256
#define TT   512
#define II   300
#define HH   64
#define G3   192
#define KP   320      // K padded: 5 chunks of 64
#define NTOT 384      // 192 fwd gates | 192 bwd gates
#define MTOT (BB * TT)

typedef unsigned long long ull;
typedef uint32_t u32;

__device__ float g_xp[2ull * TT * BB * G3];          // 201 MB scratch
__device__ float g_feat[BB * 256];
__device__ __nv_bfloat16 g_Whi[NTOT * KP];
__device__ __nv_bfloat16 g_Wlo[NTOT * KP];
__device__ __nv_bfloat16 g_xhi[(size_t)MTOT * KP];   // 80 MB
__device__ __nv_bfloat16 g_xlo[(size_t)MTOT * KP];   // 80 MB

// ---------------------------------------------------------------------------
// Helpers (all plain sm_80+ features — valid on compute_103)
// ---------------------------------------------------------------------------
__device__ __forceinline__ u32 smem_u32(const void* p) {
    u32 a;
    asm("{ .reg .u64 t; cvta.to.shared.u64 t, %1; cvt.u32.u64 %0, t; }" : "=r"(a) : "l"(p));
    return a;
}
__device__ __forceinline__ void cp16(u32 dst, const void* src) {
    asm volatile("cp.async.cg.shared.global [%0], [%1], 16;" :: "r"(dst), "l"(src));
}
#define CP_COMMIT()  asm volatile("cp.async.commit_group;" ::: "memory")
#define CP_WAIT(n)   asm volatile("cp.async.wait_group %0;" :: "n"(n) : "memory")

__device__ __forceinline__ void ldm4(u32* r, u32 addr) {
    asm volatile("ldmatrix.sync.aligned.m8n8.x4.shared.b16 {%0,%1,%2,%3}, [%4];"
                 : "=r"(r[0]), "=r"(r[1]), "=r"(r[2]), "=r"(r[3]) : "r"(addr));
}
__device__ __forceinline__ void mma_bf16(float* c, const u32* a, u32 b0, u32 b1) {
    asm volatile("mma.sync.aligned.m16n8k16.row.col.f32.bf16.bf16.f32 "
                 "{%0,%1,%2,%3}, {%4,%5,%6,%7}, {%8,%9}, {%0,%1,%2,%3};"
                 : "+f"(c[0]), "+f"(c[1]), "+f"(c[2]), "+f"(c[3])
                 : "r"(a[0]), "r"(a[1]), "r"(a[2]), "r"(a[3]), "r"(b0), "r"(b1));
}
#define SWZ(o) ((o) ^ (((o) >> 3) & 0x70))

// f32x2 (packed fp32 FFMA2) for the GRU
__device__ __forceinline__ ull ffma2(ull a, ull b, ull c) {
    ull d; asm("fma.rn.f32x2 %0, %1, %2, %3;" : "=l"(d) : "l"(a), "l"(b), "l"(c)); return d;
}
union F2U { ull u; float2 f; };
__device__ __forceinline__ float hsum2(ull a) { F2U t; t.u = a; return t.f.x + t.f.y; }

// ---------------------------------------------------------------------------
// Kernel 0a: split W_ih (both dirs) into bf16 hi/lo, K padded to 320.
// ---------------------------------------------------------------------------
__global__ void __launch_bounds__(256)
wsplit_kernel(const float* __restrict__ Wf, const float* __restrict__ Wb)
{
    int i = blockIdx.x * 256 + threadIdx.x;
    if (i >= NTOT * KP) return;
    const int n = i / KP, k = i % KP;
    float v = 0.f;
    if (k < II) v = (n < G3) ? Wf[(size_t)n * II + k] : Wb[(size_t)(n - G3) * II + k];
    __nv_bfloat16 hi = __float2bfloat16(v);
    float lo = v - __bfloat162float(hi);
    g_Whi[i] = hi;
    g_Wlo[i] = __float2bfloat16(lo);
}

// ---------------------------------------------------------------------------
// Kernel 0b: split x into bf16 hi/lo, K padded to 320. One thread = 8 cols.
// ---------------------------------------------------------------------------
__global__ void __launch_bounds__(256)
xsplit_kernel(const float* __restrict__ x)
{
    const int task = blockIdx.x * 256 + threadIdx.x;   // MTOT*40 tasks
    if (task >= MTOT * 40) return;
    const int row = task / 40;
    const int c0  = (task % 40) * 8;

    float a[8];
    const float* src = x + (size_t)row * II + c0;
    float4 v0 = make_float4(0.f, 0.f, 0.f, 0.f), v1 = v0;
    if (c0     <= 296) v0 = *(const float4*)src;
    if (c0 + 4 <= 296) v1 = *(const float4*)(src + 4);
    a[0]=v0.x; a[1]=v0.y; a[2]=v0.z; a[3]=v0.w;
    a[4]=v1.x; a[5]=v1.y; a[6]=v1.z; a[7]=v1.w;

    u32 hi[4], lo[4];
    #pragma unroll
    for (int q = 0; q < 4; q++) {
        __nv_bfloat162 h2 = __floats2bfloat162_rn(a[2*q], a[2*q+1]);
        float l0 = a[2*q]   - __bfloat162float(h2.x);
        float l1 = a[2*q+1] - __bfloat162float(h2.y);
        __nv_bfloat162 l2 = __floats2bfloat162_rn(l0, l1);
        hi[q] = *(u32*)&h2;
        lo[q] = *(u32*)&l2;
    }
    const size_t di = (size_t)row * KP + c0;
    *(uint4*)(g_xhi + di) = make_uint4(hi[0], hi[1], hi[2], hi[3]);
    *(uint4*)(g_xlo + di) = make_uint4(lo[0], lo[1], lo[2], lo[3]);
}

// ---------------------------------------------------------------------------
// Kernel 1: proj GEMM via mma.sync bf16, 3-pass split (hi*hi + hi*lo + lo*hi).
// CTA tile 128(M) x 128(N), 8 warps as 2x4 (warp tile 64x32), K-chunk 64,
// 2-stage cp.async pipeline. Smem rows = 64 bf16 = 128 B, SW128 swizzle.
// ---------------------------------------------------------------------------
#define STG_BYTES 65536          // 4 tiles x 16 KB
#define OFF_AHI 0
#define OFF_ALO 16384
#define OFF_BHI 32768
#define OFF_BLO 49152
#define PROJ_SMEM (2 * STG_BYTES + 1024)

__global__ void __launch_bounds__(256, 1)
proj_kernel(const float* __restrict__ bf_, const float* __restrict__ bb_)
{
    extern __shared__ char dyn_smem[];
    const u32 base = (smem_u32(dyn_smem) + 1023u) & ~1023u;

    const int tid    = threadIdx.x;
    const int lane   = tid & 31;
    const int wid    = tid >> 5;
    const int warp_m = wid & 1;          // 0..1
    const int warp_n = wid >> 1;         // 0..3
    const int r0     = blockIdx.x * 128; // M tile
    const int n0     = blockIdx.y * 128; // N tile

    float acc[4][4][4];
    #pragma unroll
    for (int i = 0; i < 4; i++)
        #pragma unroll
        for (int j = 0; j < 4; j++)
            #pragma unroll
            for (int q = 0; q < 4; q++) acc[i][j][q] = 0.f;

    // ---- stage loader: 4096 cp.async of 16B split over 256 threads ----
    auto load_stage = [&](int stg, int c) {
        const int k0 = c * 64;
        const u32 sb = base + stg * STG_BYTES;
        #pragma unroll
        for (int it = 0; it < 4; it++) {
            const int t = tid + it * 256;
            const int row = t >> 3, q = t & 7;
            const u32 off = SWZ((u32)(row * 128 + q * 16));
            const size_t asrc = (size_t)(r0 + row) * KP + k0 + q * 8;
            const size_t bsrc = (size_t)(n0 + row) * KP + k0 + q * 8;
            cp16(sb + OFF_AHI + off, g_xhi + asrc);
            cp16(sb + OFF_ALO + off, g_xlo + asrc);
            cp16(sb + OFF_BHI + off, g_Whi + bsrc);
            cp16(sb + OFF_BLO + off, g_Wlo + bsrc);
        }
    };

    load_stage(0, 0);
    CP_COMMIT();

    const int lr  = lane & 7;
    const int mi4 = lane >> 3;           // ldmatrix matrix index 0..3

    for (int c = 0; c < 5; c++) {
        if (c + 1 < 5) { load_stage((c + 1) & 1, c + 1); CP_COMMIT(); CP_WAIT(1); }
        else           { CP_WAIT(0); }
        __syncthreads();

        const u32 sb = base + (c & 1) * STG_BYTES;

        #pragma unroll
        for (int kk = 0; kk < 4; kk++) {
            const int kb = kk * 32 + (mi4 >> 1) * 16;

            u32 ah[4][4], al[4][4], bh[2][4], bl[2][4];
            #pragma unroll
            for (int mi = 0; mi < 4; mi++) {
                const int row = warp_m * 64 + mi * 16 + (mi4 & 1) * 8 + lr;
                const u32 off = SWZ((u32)(row * 128 + kb));
                ldm4(ah[mi], sb + OFF_AHI + off);
                ldm4(al[mi], sb + OFF_ALO + off);
            }
            #pragma unroll
            for (int g = 0; g < 2; g++) {
                const int row = warp_n * 32 + g * 16 + (mi4 & 1) * 8 + lr;
                const u32 off = SWZ((u32)(row * 128 + kb));
                ldm4(bh[g], sb + OFF_BHI + off);
                ldm4(bl[g], sb + OFF_BLO + off);
            }
            #pragma unroll
            for (int mi = 0; mi < 4; mi++)
                #pragma unroll
                for (int j = 0; j < 4; j++) {
                    const int g = j >> 1, sel = j & 1;
                    mma_bf16(acc[mi][j], ah[mi], bh[g][sel], bh[g][sel + 2]);
                    mma_bf16(acc[mi][j], ah[mi], bl[g][sel], bl[g][sel + 2]);
                    mma_bf16(acc[mi][j], al[mi], bh[g][sel], bh[g][sel + 2]);
                }
        }
        __syncthreads();
    }

    // ---- epilogue: bias + scatter to g_xp in scan order ----
    #pragma unroll
    for (int j = 0; j < 4; j++) {
        const int col = n0 + warp_n * 32 + j * 8 + (lane & 3) * 2;
        const int dir = (col >= G3) ? 1 : 0;
        const int g   = col - dir * G3;
        const float2 bv = *(const float2*)((dir ? bb_ : bf_) + g);
        #pragma unroll
        for (int mi = 0; mi < 4; mi++) {
            #pragma unroll
            for (int h = 0; h < 2; h++) {
                const int r = r0 + warp_m * 64 + mi * 16 + (lane >> 2) + h * 8;
                const int b = r >> 9, t = r & 511;
                const int s = dir ? (TT - 1 - t) : t;
                float2 o;
                o.x = acc[mi][j][2*h]   + bv.x;
                o.y = acc[mi][j][2*h+1] + bv.y;
                *(float2*)&g_xp[(((size_t)dir * TT + s) * BB + b) * G3 + g] = o;
            }
        }
    }
}

// ---------------------------------------------------------------------------
// Kernel 2: GRU recurrence, pair-split.
// Block = 128 threads = 1 chain. Thread pair (2j, 2j+1): each holds 3x32
// weights (48 f32x2 regs -> no spill), shfl_xor(1) combines partial dots.
// ---------------------------------------------------------------------------
__device__ __forceinline__ float sigmoid_fast(float a) {
    return 1.f / (1.f + __expf(-a));
}
__device__ __forceinline__ float tanh_fast(float a) {
    float c = fminf(fmaxf(a, -20.f), 20.f);
    float e = __expf(2.f * c);
    return (e - 1.f) / (e + 1.f);
}

__global__ void __launch_bounds__(128)
gru_kernel(const float* __restrict__ Whh_f, const float* __restrict__ bhh_f,
           const float* __restrict__ Whh_b, const float* __restrict__ bhh_b)
{
    __shared__ __align__(16) float sh_h[2][64];

    const int tid  = threadIdx.x;
    const int j    = tid >> 1;          // h unit 0..63
    const int half = tid & 1;           // which 32 h-inputs
    const int dir  = blockIdx.x >> 8;
    const int b    = blockIdx.x & 255;

    const float* W  = dir ? Whh_b : Whh_f;
    const float* bh = dir ? bhh_b : bhh_f;

    ull wr[16], wz[16], wn[16];
    {
        const ulonglong2* Rr = (const ulonglong2*)(W + (size_t)j * 64         + half * 32);
        const ulonglong2* Rz = (const ulonglong2*)(W + (size_t)(j + 64) * 64  + half * 32);
        const ulonglong2* Rn = (const ulonglong2*)(W + (size_t)(j + 128) * 64 + half * 32);
        #pragma unroll
        for (int q = 0; q < 8; q++) {
            ((ulonglong2*)wr)[q] = Rr[q];
            ((ulonglong2*)wz)[q] = Rz[q];
            ((ulonglong2*)wn)[q] = Rn[q];
        }
    }
    const float br = bh[j], bz = bh[j + 64], bn = bh[j + 128];

    if (tid < 64) sh_h[0][tid] = 0.f;
    float h_old = 0.f;

    const float* xp_b = g_xp + ((size_t)dir * TT * BB + b) * G3;
    const size_t stride = (size_t)BB * G3;

    float xr = __ldg(xp_b + j);
    float xz = __ldg(xp_b + j + 64);
    float xn = __ldg(xp_b + j + 128);

    __syncthreads();

    #pragma unroll 1
    for (int s = 0; s < TT; s++) {
        float nxr = 0.f, nxz = 0.f, nxn = 0.f;
        if (s + 1 < TT) {
            const float* p = xp_b + (size_t)(s + 1) * stride;
            nxr = __ldg(p + j); nxz = __ldg(p + j + 64); nxn = __ldg(p + j + 128);
        }

        const int pp = s & 1;
        const ulonglong2* hp = (const ulonglong2*)&sh_h[pp][half * 32];
        ull ar = 0ull, az = 0ull, an = 0ull;
        #pragma unroll
        for (int q = 0; q < 8; q++) {
            ulonglong2 h2 = hp[q];
            ar = ffma2(wr[2*q],   h2.x, ar);
            az = ffma2(wz[2*q],   h2.x, az);
            an = ffma2(wn[2*q],   h2.x, an);
            ar = ffma2(wr[2*q+1], h2.y, ar);
            az = ffma2(wz[2*q+1], h2.y, az);
            an = ffma2(wn[2*q+1], h2.y, an);
        }
        float gr = hsum2(ar), gz = hsum2(az), gn = hsum2(an);
        gr += __shfl_xor_sync(0xffffffffu, gr, 1);
        gz += __shfl_xor_sync(0xffffffffu, gz, 1);
        gn += __shfl_xor_sync(0xffffffffu, gn, 1);
        gr += br; gz += bz; gn += bn;

        const float r = sigmoid_fast(xr + gr);
        const float z = sigmoid_fast(xz + gz);
        const float n = tanh_fast(xn + r * gn);
        const float hnew = (1.f - z) * n + z * h_old;
        h_old = hnew;

        if (half == 0) {
            sh_h[1 - pp][j] = hnew;
            if (s == 0)
                g_feat[b * 256 + (dir ? 192 : 0) + j] = hnew;   // hs_f[0] / hs_b[0]
        }
        __syncthreads();

        xr = nxr; xz = nxz; xn = nxn;
    }

    if (half == 0)
        g_feat[b * 256 + (dir ? 64 : 128) + j] = h_old;          // final h
}

// ---------------------------------------------------------------------------
// Kernel 3: head. One warp per batch row.
// ---------------------------------------------------------------------------
__global__ void __launch_bounds__(32)
head_kernel(const float* __restrict__ W1, const float* __restrict__ b1,
            const float* __restrict__ W2, const float* __restrict__ b2,
            float* __restrict__ out)
{
    const int b = blockIdx.x;
    const int j = threadIdx.x;
    const float* f = g_feat + b * 256;
    const float* w = W1 + (size_t)j * 256;

    float acc = b1[j];
    #pragma unroll 8
    for (int k = 0; k < 256; k += 4) {
        float4 fv = *(const float4*)(f + k);
        float4 wv = *(const float4*)(w + k);
        acc += fv.x * wv.x + fv.y * wv.y + fv.z * wv.z + fv.w * wv.w;
    }
    acc = (acc >= 0.f) ? acc : 0.01f * acc;
    float v = acc * W2[j];
    #pragma unroll
    for (int off = 16; off; off >>= 1)
        v += __shfl_down_sync(0xffffffffu, v, off);
    if (j == 0) out[b] = v + b2[0];
}

// ---------------------------------------------------------------------------
extern "C" void kernel_launch(void* const* d_in, const int* in_sizes, int n_in,
                              void* d_out, int out_size)
{
    const float* x      = (const float*)d_in[0];
    const float* W_ih_f = (const float*)d_in[1];
    const float* W_hh_f = (const float*)d_in[2];
    const float* b_ih_f = (const float*)d_in[3];
    const float* b_hh_f = (const float*)d_in[4];
    const float* W_ih_b = (const float*)d_in[5];
    const float* W_hh_b = (const float*)d_in[6];
    const float* b_ih_b = (const float*)d_in[7];
    const float* b_hh_b = (const float*)d_in[8];
    const float* W1     = (const float*)d_in[9];
    const float* b1     = (const float*)d_in[10];
    const float* W2     = (const float*)d_in[11];
    const float* b2     = (const float*)d_in[12];
    float* out = (float*)d_out;

    // Not a stream operation — safe under graph capture; no static guard (rules).
    cudaFuncSetAttribute(proj_kernel, cudaFuncAttributeMaxDynamicSharedMemorySize, PROJ_SMEM);

    wsplit_kernel<<<(NTOT * KP + 255) / 256, 256>>>(W_ih_f, W_ih_b);
    xsplit_kernel<<<(MTOT * 40 + 255) / 256, 256>>>(x);
    proj_kernel<<<dim3(1024, 3), 256, PROJ_SMEM>>>(b_ih_f, b_ih_b);
    gru_kernel<<<512, 128>>>(W_hh_f, b_hh_f, W_hh_b, b_hh_b);
    head_kernel<<<256, 32>>>(W1, b1, W2, b2, out);
}

// round 7
// speedup vs baseline: 2.2886x; 1.3517x over previous
#include <cuda_runtime.h>
#include <cuda_bf16.h>
#include <cstdint>

#define BB   256
#define TT   512
#define II   300
#define HH   64
#define G3   192
#define KP   320      // K padded: 5 chunks of 64
#define NTOT 384      // 192 fwd gates | 192 bwd gates
#define MTOT (BB * TT)
#define RING_D 8      // gru xp prefetch depth (steps)

typedef unsigned long long ull;
typedef uint32_t u32;

__device__ float g_xp[2ull * TT * BB * G3];          // 201 MB scratch
__device__ float g_feat[BB * 256];
__device__ __nv_bfloat16 g_Whi[NTOT * KP];
__device__ __nv_bfloat16 g_Wlo[NTOT * KP];
__device__ __nv_bfloat16 g_xhi[(size_t)MTOT * KP];   // 80 MB
__device__ __nv_bfloat16 g_xlo[(size_t)MTOT * KP];   // 80 MB

// ---------------------------------------------------------------------------
// Helpers (plain sm_80+ features — valid on compute_103)
// ---------------------------------------------------------------------------
__device__ __forceinline__ u32 smem_u32(const void* p) {
    u32 a;
    asm("{ .reg .u64 t; cvta.to.shared.u64 t, %1; cvt.u32.u64 %0, t; }" : "=r"(a) : "l"(p));
    return a;
}
__device__ __forceinline__ void cp16(u32 dst, const void* src) {
    asm volatile("cp.async.cg.shared.global [%0], [%1], 16;" :: "r"(dst), "l"(src));
}
#define CP_COMMIT()  asm volatile("cp.async.commit_group;" ::: "memory")
#define CP_WAIT(n)   asm volatile("cp.async.wait_group %0;" :: "n"(n) : "memory")

__device__ __forceinline__ void ldm4(u32* r, u32 addr) {
    asm volatile("ldmatrix.sync.aligned.m8n8.x4.shared.b16 {%0,%1,%2,%3}, [%4];"
                 : "=r"(r[0]), "=r"(r[1]), "=r"(r[2]), "=r"(r[3]) : "r"(addr));
}
__device__ __forceinline__ void mma_bf16(float* c, const u32* a, u32 b0, u32 b1) {
    asm volatile("mma.sync.aligned.m16n8k16.row.col.f32.bf16.bf16.f32 "
                 "{%0,%1,%2,%3}, {%4,%5,%6,%7}, {%8,%9}, {%0,%1,%2,%3};"
                 : "+f"(c[0]), "+f"(c[1]), "+f"(c[2]), "+f"(c[3])
                 : "r"(a[0]), "r"(a[1]), "r"(a[2]), "r"(a[3]), "r"(b0), "r"(b1));
}
#define SWZ(o) ((o) ^ (((o) >> 3) & 0x70))

// f32x2 (packed fp32 FFMA2) for the GRU
__device__ __forceinline__ ull ffma2(ull a, ull b, ull c) {
    ull d; asm("fma.rn.f32x2 %0, %1, %2, %3;" : "=l"(d) : "l"(a), "l"(b), "l"(c)); return d;
}
union F2U { ull u; float2 f; };
__device__ __forceinline__ float hsum2(ull a) { F2U t; t.u = a; return t.f.x + t.f.y; }

// ---------------------------------------------------------------------------
// Kernel 0a: split W_ih (both dirs) into bf16 hi/lo, K padded to 320.
// ---------------------------------------------------------------------------
__global__ void __launch_bounds__(256)
wsplit_kernel(const float* __restrict__ Wf, const float* __restrict__ Wb)
{
    int i = blockIdx.x * 256 + threadIdx.x;
    if (i >= NTOT * KP) return;
    const int n = i / KP, k = i % KP;
    float v = 0.f;
    if (k < II) v = (n < G3) ? Wf[(size_t)n * II + k] : Wb[(size_t)(n - G3) * II + k];
    __nv_bfloat16 hi = __float2bfloat16(v);
    float lo = v - __bfloat162float(hi);
    g_Whi[i] = hi;
    g_Wlo[i] = __float2bfloat16(lo);
}

// ---------------------------------------------------------------------------
// Kernel 0b: split x into bf16 hi/lo, K padded to 320. One thread = 8 cols.
// ---------------------------------------------------------------------------
__global__ void __launch_bounds__(256)
xsplit_kernel(const float* __restrict__ x)
{
    const int task = blockIdx.x * 256 + threadIdx.x;   // MTOT*40 tasks
    if (task >= MTOT * 40) return;
    const int row = task / 40;
    const int c0  = (task % 40) * 8;

    float a[8];
    const float* src = x + (size_t)row * II + c0;
    float4 v0 = make_float4(0.f, 0.f, 0.f, 0.f), v1 = v0;
    if (c0     <= 296) v0 = *(const float4*)src;
    if (c0 + 4 <= 296) v1 = *(const float4*)(src + 4);
    a[0]=v0.x; a[1]=v0.y; a[2]=v0.z; a[3]=v0.w;
    a[4]=v1.x; a[5]=v1.y; a[6]=v1.z; a[7]=v1.w;

    u32 hi[4], lo[4];
    #pragma unroll
    for (int q = 0; q < 4; q++) {
        __nv_bfloat162 h2 = __floats2bfloat162_rn(a[2*q], a[2*q+1]);
        float l0 = a[2*q]   - __bfloat162float(h2.x);
        float l1 = a[2*q+1] - __bfloat162float(h2.y);
        __nv_bfloat162 l2 = __floats2bfloat162_rn(l0, l1);
        hi[q] = *(u32*)&h2;
        lo[q] = *(u32*)&l2;
    }
    const size_t di = (size_t)row * KP + c0;
    *(uint4*)(g_xhi + di) = make_uint4(hi[0], hi[1], hi[2], hi[3]);
    *(uint4*)(g_xlo + di) = make_uint4(lo[0], lo[1], lo[2], lo[3]);
}

// ---------------------------------------------------------------------------
// Kernel 1: proj GEMM via mma.sync bf16, 3-pass split (hi*hi + hi*lo + lo*hi).
// CTA tile 128(M) x 128(N), 8 warps as 2x4 (warp tile 64x32), K-chunk 64,
// 2-stage cp.async pipeline. Grid (3 N-tiles fastest, 1024 M-tiles) so the 3
// blocks sharing an A tile run adjacently -> A served from L2 (2 of 3 reads).
// ---------------------------------------------------------------------------
#define STG_BYTES 65536          // 4 tiles x 16 KB
#define OFF_AHI 0
#define OFF_ALO 16384
#define OFF_BHI 32768
#define OFF_BLO 49152
#define PROJ_SMEM (2 * STG_BYTES + 1024)

__global__ void __launch_bounds__(256, 1)
proj_kernel(const float* __restrict__ bf_, const float* __restrict__ bb_)
{
    extern __shared__ char dyn_smem[];
    const u32 base = (smem_u32(dyn_smem) + 1023u) & ~1023u;

    const int tid    = threadIdx.x;
    const int lane   = tid & 31;
    const int wid    = tid >> 5;
    const int warp_m = wid & 1;          // 0..1
    const int warp_n = wid >> 1;         // 0..3
    const int r0     = blockIdx.y * 128; // M tile
    const int n0     = blockIdx.x * 128; // N tile (fastest -> L2 A reuse)

    float acc[4][4][4];
    #pragma unroll
    for (int i = 0; i < 4; i++)
        #pragma unroll
        for (int j = 0; j < 4; j++)
            #pragma unroll
            for (int q = 0; q < 4; q++) acc[i][j][q] = 0.f;

    auto load_stage = [&](int stg, int c) {
        const int k0 = c * 64;
        const u32 sb = base + stg * STG_BYTES;
        #pragma unroll
        for (int it = 0; it < 4; it++) {
            const int t = tid + it * 256;
            const int row = t >> 3, q = t & 7;
            const u32 off = SWZ((u32)(row * 128 + q * 16));
            const size_t asrc = (size_t)(r0 + row) * KP + k0 + q * 8;
            const size_t bsrc = (size_t)(n0 + row) * KP + k0 + q * 8;
            cp16(sb + OFF_AHI + off, g_xhi + asrc);
            cp16(sb + OFF_ALO + off, g_xlo + asrc);
            cp16(sb + OFF_BHI + off, g_Whi + bsrc);
            cp16(sb + OFF_BLO + off, g_Wlo + bsrc);
        }
    };

    load_stage(0, 0);
    CP_COMMIT();

    const int lr  = lane & 7;
    const int mi4 = lane >> 3;

    for (int c = 0; c < 5; c++) {
        if (c + 1 < 5) { load_stage((c + 1) & 1, c + 1); CP_COMMIT(); CP_WAIT(1); }
        else           { CP_WAIT(0); }
        __syncthreads();

        const u32 sb = base + (c & 1) * STG_BYTES;

        #pragma unroll
        for (int kk = 0; kk < 4; kk++) {
            const int kb = kk * 32 + (mi4 >> 1) * 16;

            u32 ah[4][4], al[4][4], bh[2][4], bl[2][4];
            #pragma unroll
            for (int mi = 0; mi < 4; mi++) {
                const int row = warp_m * 64 + mi * 16 + (mi4 & 1) * 8 + lr;
                const u32 off = SWZ((u32)(row * 128 + kb));
                ldm4(ah[mi], sb + OFF_AHI + off);
                ldm4(al[mi], sb + OFF_ALO + off);
            }
            #pragma unroll
            for (int g = 0; g < 2; g++) {
                const int row = warp_n * 32 + g * 16 + (mi4 & 1) * 8 + lr;
                const u32 off = SWZ((u32)(row * 128 + kb));
                ldm4(bh[g], sb + OFF_BHI + off);
                ldm4(bl[g], sb + OFF_BLO + off);
            }
            #pragma unroll
            for (int mi = 0; mi < 4; mi++)
                #pragma unroll
                for (int j = 0; j < 4; j++) {
                    const int g = j >> 1, sel = j & 1;
                    mma_bf16(acc[mi][j], ah[mi], bh[g][sel], bh[g][sel + 2]);
                    mma_bf16(acc[mi][j], ah[mi], bl[g][sel], bl[g][sel + 2]);
                    mma_bf16(acc[mi][j], al[mi], bh[g][sel], bh[g][sel + 2]);
                }
        }
        __syncthreads();
    }

    // ---- epilogue: bias + scatter to g_xp in scan order ----
    #pragma unroll
    for (int j = 0; j < 4; j++) {
        const int col = n0 + warp_n * 32 + j * 8 + (lane & 3) * 2;
        const int dir = (col >= G3) ? 1 : 0;
        const int g   = col - dir * G3;
        const float2 bv = *(const float2*)((dir ? bb_ : bf_) + g);
        #pragma unroll
        for (int mi = 0; mi < 4; mi++) {
            #pragma unroll
            for (int h = 0; h < 2; h++) {
                const int r = r0 + warp_m * 64 + mi * 16 + (lane >> 2) + h * 8;
                const int b = r >> 9, t = r & 511;
                const int s = dir ? (TT - 1 - t) : t;
                float2 o;
                o.x = acc[mi][j][2*h]   + bv.x;
                o.y = acc[mi][j][2*h+1] + bv.y;
                *(float2*)&g_xp[(((size_t)dir * TT + s) * BB + b) * G3 + g] = o;
            }
        }
    }
}

// ---------------------------------------------------------------------------
// Kernel 2: GRU recurrence, pair-split + cp.async xp ring.
// Block = 128 threads = 1 chain. Thread pair (2j, 2j+1): each holds 3x32
// weights (48 f32x2 regs), shfl_xor(1) combines partials.
// xp streamed through a depth-8 cp.async smem ring (threads 0..47 load
// 16B each per step) -> DRAM latency covered by 8 step-times.
// One wait_group + one __syncthreads per step; prefetch issued after the
// barrier so slot reuse is race-free. launch_bounds(128,4): 4 blocks/SM
// -> 592 slots >= 512 blocks -> single wave.
// ---------------------------------------------------------------------------
__device__ __forceinline__ float sigmoid_fast(float a) {
    return 1.f / (1.f + __expf(-a));
}
__device__ __forceinline__ float tanh_fast(float a) {
    float c = fminf(fmaxf(a, -20.f), 20.f);
    float e = __expf(2.f * c);
    return (e - 1.f) / (e + 1.f);
}

__global__ void __launch_bounds__(128, 4)
gru_kernel(const float* __restrict__ Whh_f, const float* __restrict__ bhh_f,
           const float* __restrict__ Whh_b, const float* __restrict__ bhh_b)
{
    __shared__ __align__(16) float sh_h[2][64];
    __shared__ __align__(16) float ring[RING_D][192];

    const int tid  = threadIdx.x;
    const int j    = tid >> 1;          // h unit 0..63
    const int half = tid & 1;           // which 32 h-inputs
    const int dir  = blockIdx.x >> 8;
    const int b    = blockIdx.x & 255;

    const float* W  = dir ? Whh_b : Whh_f;
    const float* bh = dir ? bhh_b : bhh_f;

    ull wr[16], wz[16], wn[16];
    {
        const ulonglong2* Rr = (const ulonglong2*)(W + (size_t)j * 64         + half * 32);
        const ulonglong2* Rz = (const ulonglong2*)(W + (size_t)(j + 64) * 64  + half * 32);
        const ulonglong2* Rn = (const ulonglong2*)(W + (size_t)(j + 128) * 64 + half * 32);
        #pragma unroll
        for (int q = 0; q < 8; q++) {
            ((ulonglong2*)wr)[q] = Rr[q];
            ((ulonglong2*)wz)[q] = Rz[q];
            ((ulonglong2*)wn)[q] = Rn[q];
        }
    }
    const float br = bh[j], bz = bh[j + 64], bn = bh[j + 128];

    if (tid < 64) sh_h[0][tid] = 0.f;
    float h_old = 0.f;

    const float* xp_b = g_xp + ((size_t)dir * TT * BB + b) * G3;
    const size_t stride = (size_t)BB * G3;
    const u32 ring_base = smem_u32(ring);

    // Prologue: fill ring with steps 0..RING_D-1 (one group per step).
    #pragma unroll
    for (int d = 0; d < RING_D; d++) {
        if (tid < 48)
            cp16(ring_base + (u32)(d * 768 + tid * 16),
                 xp_b + (size_t)d * stride + tid * 4);
        CP_COMMIT();
    }
    CP_WAIT(RING_D - 1);    // slot 0 complete (loader threads)
    __syncthreads();        // slot 0 + sh_h visible to all

    #pragma unroll 1
    for (int s = 0; s < TT; s++) {
        // invariant: ring slot s%D complete & visible; sh_h[s&1] valid
        const int slot = s & (RING_D - 1);
        const float* xp = ring[slot];
        const float xr = xp[j];
        const float xz = xp[j + 64];
        const float xn = xp[j + 128];

        const int pp = s & 1;
        const ulonglong2* hp = (const ulonglong2*)&sh_h[pp][half * 32];
        ull ar = 0ull, az = 0ull, an = 0ull;
        #pragma unroll
        for (int q = 0; q < 8; q++) {
            ulonglong2 h2 = hp[q];
            ar = ffma2(wr[2*q],   h2.x, ar);
            az = ffma2(wz[2*q],   h2.x, az);
            an = ffma2(wn[2*q],   h2.x, an);
            ar = ffma2(wr[2*q+1], h2.y, ar);
            az = ffma2(wz[2*q+1], h2.y, az);
            an = ffma2(wn[2*q+1], h2.y, an);
        }
        float gr = hsum2(ar), gz = hsum2(az), gn = hsum2(an);
        gr += __shfl_xor_sync(0xffffffffu, gr, 1);
        gz += __shfl_xor_sync(0xffffffffu, gz, 1);
        gn += __shfl_xor_sync(0xffffffffu, gn, 1);
        gr += br; gz += bz; gn += bn;

        const float r = sigmoid_fast(xr + gr);
        const float z = sigmoid_fast(xz + gz);
        const float n = tanh_fast(xn + r * gn);
        const float hnew = (1.f - z) * n + z * h_old;
        h_old = hnew;

        if (half == 0) {
            sh_h[1 - pp][j] = hnew;
            if (s == 0)
                g_feat[b * 256 + (dir ? 192 : 0) + j] = hnew;   // hs_f[0] / hs_b[0]
        }

        // slot s+1 must be done before next iter; slot s%D reads all done after bar
        CP_WAIT(RING_D - 2);
        __syncthreads();

        // refill slot s%D with step (s+RING_D)%TT (wraps to old data near the
        // end — valid memory, never consumed; keeps group counts uniform)
        if (tid < 48)
            cp16(ring_base + (u32)(slot * 768 + tid * 16),
                 xp_b + (size_t)((s + RING_D) & (TT - 1)) * stride + tid * 4);
        CP_COMMIT();
    }

    if (half == 0)
        g_feat[b * 256 + (dir ? 64 : 128) + j] = h_old;          // final h
}

// ---------------------------------------------------------------------------
// Kernel 3: head. One warp per batch row.
// ---------------------------------------------------------------------------
__global__ void __launch_bounds__(32)
head_kernel(const float* __restrict__ W1, const float* __restrict__ b1,
            const float* __restrict__ W2, const float* __restrict__ b2,
            float* __restrict__ out)
{
    const int b = blockIdx.x;
    const int j = threadIdx.x;
    const float* f = g_feat + b * 256;
    const float* w = W1 + (size_t)j * 256;

    float acc = b1[j];
    #pragma unroll 8
    for (int k = 0; k < 256; k += 4) {
        float4 fv = *(const float4*)(f + k);
        float4 wv = *(const float4*)(w + k);
        acc += fv.x * wv.x + fv.y * wv.y + fv.z * wv.z + fv.w * wv.w;
    }
    acc = (acc >= 0.f) ? acc : 0.01f * acc;
    float v = acc * W2[j];
    #pragma unroll
    for (int off = 16; off; off >>= 1)
        v += __shfl_down_sync(0xffffffffu, v, off);
    if (j == 0) out[b] = v + b2[0];
}

// ---------------------------------------------------------------------------
extern "C" void kernel_launch(void* const* d_in, const int* in_sizes, int n_in,
                              void* d_out, int out_size)
{
    const float* x      = (const float*)d_in[0];
    const float* W_ih_f = (const float*)d_in[1];
    const float* W_hh_f = (const float*)d_in[2];
    const float* b_ih_f = (const float*)d_in[3];
    const float* b_hh_f = (const float*)d_in[4];
    const float* W_ih_b = (const float*)d_in[5];
    const float* W_hh_b = (const float*)d_in[6];
    const float* b_ih_b = (const float*)d_in[7];
    const float* b_hh_b = (const float*)d_in[8];
    const float* W1     = (const float*)d_in[9];
    const float* b1     = (const float*)d_in[10];
    const float* W2     = (const float*)d_in[11];
    const float* b2     = (const float*)d_in[12];
    float* out = (float*)d_out;

    cudaFuncSetAttribute(proj_kernel, cudaFuncAttributeMaxDynamicSharedMemorySize, PROJ_SMEM);

    wsplit_kernel<<<(NTOT * KP + 255) / 256, 256>>>(W_ih_f, W_ih_b);
    xsplit_kernel<<<(MTOT * 40 + 255) / 256, 256>>>(x);
    proj_kernel<<<dim3(3, 1024), 256, PROJ_SMEM>>>(b_ih_f, b_ih_b);
    gru_kernel<<<512, 128>>>(W_hh_f, b_hh_f, W_hh_b, b_hh_b);
    head_kernel<<<256, 32>>>(W1, b1, W2, b2, out);
}